// round 1
// baseline (speedup 1.0000x reference)
#include <cuda_runtime.h>
#include <cuda_bf16.h>

// Problem sizes (fixed by the reference)
#define PP 16384
#define DD 1024
#define KK 16384
#define LL 128
#define SPLITK 4

// Static scratch (no runtime allocation allowed)
__device__ float g_part[SPLITK][DD * DD];   // split-K partials of X^T X (16 MB)
__device__ float g_sigma[DD * DD];          // Sigma' = X^T X (4 MB)
__device__ float g_upart[32][DD];           // partials of X^T y
__device__ float g_w[2][DD];                // Neumann iterate (ping-pong)
__device__ float g_s[DD];                   // accumulated S @ (X^T y)

// ---------------------------------------------------------------------------
// Kernel 1: partial X^T y.  grid (4, 32) x 256 threads.
// Block (bx, z): rows r in [bx*256, bx*256+256), p in [z*512, (z+1)*512).
// ---------------------------------------------------------------------------
__global__ void xty_kernel(const float* __restrict__ X, const float* __restrict__ y) {
    int r = blockIdx.x * 256 + threadIdx.x;   // 0..1023
    int z = blockIdx.y;                        // 0..31
    float acc = 0.f;
    int p0 = z * (PP / 32);
    int p1 = p0 + (PP / 32);
    #pragma unroll 4
    for (int p = p0; p < p1; p++)
        acc += X[(size_t)p * DD + r] * y[p];   // coalesced across r
    g_upart[z][r] = acc;
}

// ---------------------------------------------------------------------------
// Kernel 2: reduce X^T y partials; init w0 = u, s = 0.  grid 4 x 256.
// ---------------------------------------------------------------------------
__global__ void init_kernel() {
    int r = blockIdx.x * 256 + threadIdx.x;
    float acc = 0.f;
    #pragma unroll
    for (int z = 0; z < 32; z++) acc += g_upart[z][r];
    g_w[0][r] = acc;
    g_s[r] = 0.f;
}

// ---------------------------------------------------------------------------
// Kernel 3: Sigma' = X^T X, symmetric tiles + split-K.
// grid (36, SPLITK), 256 threads. BM=BN=128, BK=8, TM=TN=8.
// Block b maps to triangular tile (bi <= bj) over an 8x8 tile grid.
// ---------------------------------------------------------------------------
__global__ __launch_bounds__(256, 1) void syrk_kernel(const float* __restrict__ X) {
    const int BM = 128, BK = 8, TM = 8, TN = 8;
    __shared__ float As[BK][BM];
    __shared__ float Bs[BK][BM];

    // triangular tile mapping
    int b = blockIdx.x;
    int bi = 0, t = b, rem = 8;
    while (t >= rem) { t -= rem; rem--; bi++; }
    int bj = bi + t;
    int i0 = bi * BM, j0 = bj * BM;

    int z = blockIdx.y;
    int p0 = z * (PP / SPLITK);

    int tid = threadIdx.x;
    int tx = tid % 16, ty = tid / 16;
    int lr = tid / 32;            // 0..7 : k-row within BK
    int lc4 = (tid % 32) * 4;     // 0..124 : col (float4)

    float acc[TM][TN];
    #pragma unroll
    for (int m = 0; m < TM; m++)
        #pragma unroll
        for (int n = 0; n < TN; n++) acc[m][n] = 0.f;

    for (int kb = 0; kb < PP / SPLITK; kb += BK) {
        const float* xp = X + (size_t)(p0 + kb + lr) * DD;
        float4 av = *(const float4*)(xp + i0 + lc4);
        float4 bv = *(const float4*)(xp + j0 + lc4);
        *(float4*)&As[lr][lc4] = av;
        *(float4*)&Bs[lr][lc4] = bv;
        __syncthreads();
        #pragma unroll
        for (int k = 0; k < BK; k++) {
            float ra[TM], rb[TN];
            #pragma unroll
            for (int m = 0; m < TM; m++) ra[m] = As[k][ty * TM + m];
            #pragma unroll
            for (int n = 0; n < TN; n++) rb[n] = Bs[k][tx * TN + n];
            #pragma unroll
            for (int m = 0; m < TM; m++)
                #pragma unroll
                for (int n = 0; n < TN; n++)
                    acc[m][n] += ra[m] * rb[n];
        }
        __syncthreads();
    }

    float* part = g_part[z];
    #pragma unroll
    for (int m = 0; m < TM; m++) {
        int gi = i0 + ty * TM + m;
        #pragma unroll
        for (int n = 0; n < TN; n++) {
            int gj = j0 + tx * TN + n;
            float v = acc[m][n];
            part[(size_t)gi * DD + gj] = v;
            if (bi != bj) part[(size_t)gj * DD + gi] = v;
        }
    }
}

// ---------------------------------------------------------------------------
// Kernel 4: reduce split-K partials into g_sigma. grid 1024 x 256 (float4).
// ---------------------------------------------------------------------------
__global__ void sigred_kernel() {
    int i = blockIdx.x * 256 + threadIdx.x;   // float4 index, 262144 total
    const float4* p0 = (const float4*)g_part[0];
    const float4* p1 = (const float4*)g_part[1];
    const float4* p2 = (const float4*)g_part[2];
    const float4* p3 = (const float4*)g_part[3];
    float4 a = p0[i], b = p1[i], c = p2[i], d = p3[i];
    float4 r;
    r.x = a.x + b.x + c.x + d.x;
    r.y = a.y + b.y + c.y + d.y;
    r.z = a.z + b.z + c.z + d.z;
    r.w = a.w + b.w + c.w + d.w;
    ((float4*)g_sigma)[i] = r;
}

// ---------------------------------------------------------------------------
// Kernel 5: one Neumann step.  grid 128 x 256 (1024 warps; warp r owns row r).
//   s[r] += w[r];  w'[r] = w[r] - c * dot(Sigma'[r,:], w),  c = gamma/(L*P)
// ---------------------------------------------------------------------------
__global__ void iter_kernel(const float* __restrict__ gamma, int par) {
    __shared__ float ws[DD];
    const float* w = g_w[par];
    float* wn = g_w[par ^ 1];
    int t = threadIdx.x;
    #pragma unroll
    for (int i = t; i < DD; i += 256) ws[i] = w[i];
    __syncthreads();

    int warp = blockIdx.x * 8 + (t >> 5);   // global row 0..1023
    int lane = t & 31;
    const float4* row4 = (const float4*)(g_sigma + (size_t)warp * DD);
    const float4* w4 = (const float4*)ws;
    float acc = 0.f;
    #pragma unroll
    for (int j = lane; j < DD / 4; j += 32) {
        float4 a = row4[j], bv = w4[j];
        acc += a.x * bv.x + a.y * bv.y + a.z * bv.z + a.w * bv.w;
    }
    #pragma unroll
    for (int o = 16; o; o >>= 1) acc += __shfl_xor_sync(0xffffffffu, acc, o);
    if (lane == 0) {
        float c = (*gamma) * (1.0f / ((float)LL * (float)PP));
        float wv = ws[warp];
        g_s[warp] += wv;
        wn[warp] = wv - c * acc;
    }
}

// ---------------------------------------------------------------------------
// Kernel 6: predictions = (gamma/(L*P)) * (X_star @ s) + bias.
// grid 2048 x 256 (warp per output row).
// ---------------------------------------------------------------------------
__global__ void pred_kernel(const float* __restrict__ Xs,
                            const float* __restrict__ gamma,
                            const float* __restrict__ bias,
                            float* __restrict__ out) {
    __shared__ float ss[DD];
    int t = threadIdx.x;
    #pragma unroll
    for (int i = t; i < DD; i += 256) ss[i] = g_s[i];
    __syncthreads();

    int warp = blockIdx.x * 8 + (t >> 5);   // 0..16383
    int lane = t & 31;
    const float4* row4 = (const float4*)(Xs + (size_t)warp * DD);
    const float4* s4 = (const float4*)ss;
    float acc = 0.f;
    #pragma unroll
    for (int j = lane; j < DD / 4; j += 32) {
        float4 a = row4[j], bv = s4[j];
        acc += a.x * bv.x + a.y * bv.y + a.z * bv.z + a.w * bv.w;
    }
    #pragma unroll
    for (int o = 16; o; o >>= 1) acc += __shfl_xor_sync(0xffffffffu, acc, o);
    if (lane == 0) {
        float sc = (*gamma) * (1.0f / ((float)LL * (float)PP));
        out[warp] = sc * acc + (*bias);
    }
}

// ---------------------------------------------------------------------------
extern "C" void kernel_launch(void* const* d_in, const int* in_sizes, int n_in,
                              void* d_out, int out_size) {
    const float* X     = (const float*)d_in[0];
    const float* y     = (const float*)d_in[1];
    const float* Xs    = (const float*)d_in[2];
    const float* gamma = (const float*)d_in[3];
    const float* bias  = (const float*)d_in[4];
    float* out = (float*)d_out;

    xty_kernel<<<dim3(4, 32), 256>>>(X, y);
    init_kernel<<<4, 256>>>();
    syrk_kernel<<<dim3(36, SPLITK), 256>>>(X);
    sigred_kernel<<<1024, 256>>>();
    for (int l = 0; l < LL; l++)
        iter_kernel<<<128, 256>>>(gamma, l & 1);
    pred_kernel<<<2048, 256>>>(Xs, gamma, bias, out);
}

// round 2
// speedup vs baseline: 1.3618x; 1.3618x over previous
#include <cuda_runtime.h>
#include <cuda_bf16.h>

// Problem sizes (fixed by the reference)
#define PP 16384
#define DD 1024
#define KK 16384
#define LL 128
#define SPLITK 8

// Static scratch (no runtime allocation allowed)
__device__ float g_part[SPLITK][DD * DD];            // split-K partials of X^T X (32 MB)
__device__ float g_sigma[DD * DD];                   // Sigma' = X^T X (4 MB)
__device__ float g_upart[32][DD];                    // partials of X^T y
__device__ unsigned long long g_wt[2][DD];           // tagged Neumann iterate {tag,val}
__device__ float g_s[DD];                            // accumulated S @ (X^T y)

// ---------------------------------------------------------------------------
// Kernel 1: partial X^T y.  grid (4, 32) x 256 threads.
// ---------------------------------------------------------------------------
__global__ void xty_kernel(const float* __restrict__ X, const float* __restrict__ y) {
    int r = blockIdx.x * 256 + threadIdx.x;   // 0..1023
    int z = blockIdx.y;                        // 0..31
    float acc = 0.f;
    int p0 = z * (PP / 32);
    int p1 = p0 + (PP / 32);
    #pragma unroll 4
    for (int p = p0; p < p1; p++)
        acc += X[(size_t)p * DD + r] * y[p];   // coalesced across r
    g_upart[z][r] = acc;
}

// ---------------------------------------------------------------------------
// Kernel 2: reduce X^T y partials; write tagged w0 (tag=0) into buffer 0.
// ---------------------------------------------------------------------------
__global__ void init_kernel() {
    int r = blockIdx.x * 256 + threadIdx.x;
    float acc = 0.f;
    #pragma unroll
    for (int z = 0; z < 32; z++) acc += g_upart[z][r];
    unsigned long long u = (unsigned long long)__float_as_uint(acc); // tag 0 in high bits
    *((volatile unsigned long long*)&g_wt[0][r]) = u;
}

// ---------------------------------------------------------------------------
// Kernel 3: Sigma' = X^T X, symmetric tiles + split-K.
// grid (36, SPLITK), 256 threads, 2 blocks/SM. BM=BN=128, BK=8, TM=TN=8.
// ---------------------------------------------------------------------------
__global__ __launch_bounds__(256, 2) void syrk_kernel(const float* __restrict__ X) {
    const int BM = 128, BK = 8, TM = 8, TN = 8;
    __shared__ float As[BK][BM];
    __shared__ float Bs[BK][BM];

    // triangular tile mapping (bi <= bj over an 8x8 tile grid)
    int b = blockIdx.x;
    int bi = 0, t = b, rem = 8;
    while (t >= rem) { t -= rem; rem--; bi++; }
    int bj = bi + t;
    int i0 = bi * BM, j0 = bj * BM;

    int z = blockIdx.y;
    int p0 = z * (PP / SPLITK);

    int tid = threadIdx.x;
    int tx = tid % 16, ty = tid / 16;
    int lr = tid / 32;            // 0..7 : k-row within BK
    int lc4 = (tid % 32) * 4;     // 0..124 : col (float4)

    float acc[TM][TN];
    #pragma unroll
    for (int m = 0; m < TM; m++)
        #pragma unroll
        for (int n = 0; n < TN; n++) acc[m][n] = 0.f;

    for (int kb = 0; kb < PP / SPLITK; kb += BK) {
        const float* xp = X + (size_t)(p0 + kb + lr) * DD;
        float4 av = *(const float4*)(xp + i0 + lc4);
        float4 bv = *(const float4*)(xp + j0 + lc4);
        *(float4*)&As[lr][lc4] = av;
        *(float4*)&Bs[lr][lc4] = bv;
        __syncthreads();
        #pragma unroll
        for (int k = 0; k < BK; k++) {
            float ra[TM], rb[TN];
            #pragma unroll
            for (int m = 0; m < TM; m++) ra[m] = As[k][ty * TM + m];
            #pragma unroll
            for (int n = 0; n < TN; n++) rb[n] = Bs[k][tx * TN + n];
            #pragma unroll
            for (int m = 0; m < TM; m++)
                #pragma unroll
                for (int n = 0; n < TN; n++)
                    acc[m][n] += ra[m] * rb[n];
        }
        __syncthreads();
    }

    float* part = g_part[z];
    #pragma unroll
    for (int m = 0; m < TM; m++) {
        int gi = i0 + ty * TM + m;
        #pragma unroll
        for (int n = 0; n < TN; n++) {
            int gj = j0 + tx * TN + n;
            float v = acc[m][n];
            part[(size_t)gi * DD + gj] = v;
            if (bi != bj) part[(size_t)gj * DD + gi] = v;
        }
    }
}

// ---------------------------------------------------------------------------
// Kernel 4: reduce split-K partials into g_sigma. grid 1024 x 256 (float4).
// ---------------------------------------------------------------------------
__global__ void sigred_kernel() {
    int i = blockIdx.x * 256 + threadIdx.x;   // float4 index, 262144 total
    float4 r = ((const float4*)g_part[0])[i];
    #pragma unroll
    for (int z = 1; z < SPLITK; z++) {
        float4 a = ((const float4*)g_part[z])[i];
        r.x += a.x; r.y += a.y; r.z += a.z; r.w += a.w;
    }
    ((float4*)g_sigma)[i] = r;
}

// ---------------------------------------------------------------------------
// Kernel 5: persistent Neumann chain — ALL 128 iterations in one launch.
// grid 128 x 256 (1024 warps; warp r owns row r). Dataflow sync via tagged
// 8-byte stores (tag = iteration), ping-ponged over two buffers. No grid
// barrier, no fences: Sigma row lives in registers for the whole kernel.
//   s[r] += w_l[r];  w_{l+1}[r] = w_l[r] - c * dot(Sigma[r,:], w_l)
// ---------------------------------------------------------------------------
__global__ __launch_bounds__(256, 1) void neumann_kernel(const float* __restrict__ gamma) {
    __shared__ float ws[DD];
    int t = threadIdx.x;
    int warp = blockIdx.x * 8 + (t >> 5);   // global row 0..1023
    int lane = t & 31;

    float c = (*gamma) * (1.0f / ((float)LL * (float)PP));

    // Load this warp's Sigma row into registers (constant across iterations).
    const float4* row4 = (const float4*)(g_sigma + (size_t)warp * DD);
    float4 a[8];
    #pragma unroll
    for (int i = 0; i < 8; i++) a[i] = row4[i * 32 + lane];

    float s_acc = 0.f;

    for (int l = 0; l < LL; l++) {
        // Poll w_l (tag == l) into shared: thread t covers 4 elements, coalesced.
        volatile unsigned long long* win = (volatile unsigned long long*)g_wt[l & 1];
        #pragma unroll
        for (int k = 0; k < 4; k++) {
            int j = t + 256 * k;
            unsigned long long u;
            do { u = win[j]; } while ((unsigned)(u >> 32) != (unsigned)l);
            ws[j] = __uint_as_float((unsigned)u);
        }
        __syncthreads();

        // dot(Sigma[warp,:], w_l)
        const float4* w4 = (const float4*)ws;
        float acc = 0.f;
        #pragma unroll
        for (int i = 0; i < 8; i++) {
            float4 bv = w4[i * 32 + lane];
            acc += a[i].x * bv.x + a[i].y * bv.y + a[i].z * bv.z + a[i].w * bv.w;
        }
        #pragma unroll
        for (int o = 16; o; o >>= 1) acc += __shfl_xor_sync(0xffffffffu, acc, o);

        if (lane == 0) {
            float wv = ws[warp];
            s_acc += wv;
            float wn = wv - c * acc;
            unsigned long long u = ((unsigned long long)(unsigned)(l + 1) << 32)
                                 | (unsigned long long)__float_as_uint(wn);
            *((volatile unsigned long long*)&g_wt[(l + 1) & 1][warp]) = u;
        }
        __syncthreads();   // protect ws before next iteration's poll overwrites it
    }

    if (lane == 0) g_s[warp] = s_acc;
}

// ---------------------------------------------------------------------------
// Kernel 6: predictions = (gamma/(L*P)) * (X_star @ s) + bias.
// grid 2048 x 256 (warp per output row).
// ---------------------------------------------------------------------------
__global__ void pred_kernel(const float* __restrict__ Xs,
                            const float* __restrict__ gamma,
                            const float* __restrict__ bias,
                            float* __restrict__ out) {
    __shared__ float ss[DD];
    int t = threadIdx.x;
    #pragma unroll
    for (int i = t; i < DD; i += 256) ss[i] = g_s[i];
    __syncthreads();

    int warp = blockIdx.x * 8 + (t >> 5);   // 0..16383
    int lane = t & 31;
    const float4* row4 = (const float4*)(Xs + (size_t)warp * DD);
    const float4* s4 = (const float4*)ss;
    float acc = 0.f;
    #pragma unroll
    for (int j = lane; j < DD / 4; j += 32) {
        float4 a = row4[j], bv = s4[j];
        acc += a.x * bv.x + a.y * bv.y + a.z * bv.z + a.w * bv.w;
    }
    #pragma unroll
    for (int o = 16; o; o >>= 1) acc += __shfl_xor_sync(0xffffffffu, acc, o);
    if (lane == 0) {
        float sc = (*gamma) * (1.0f / ((float)LL * (float)PP));
        out[warp] = sc * acc + (*bias);
    }
}

// ---------------------------------------------------------------------------
extern "C" void kernel_launch(void* const* d_in, const int* in_sizes, int n_in,
                              void* d_out, int out_size) {
    const float* X     = (const float*)d_in[0];
    const float* y     = (const float*)d_in[1];
    const float* Xs    = (const float*)d_in[2];
    const float* gamma = (const float*)d_in[3];
    const float* bias  = (const float*)d_in[4];
    float* out = (float*)d_out;

    xty_kernel<<<dim3(4, 32), 256>>>(X, y);
    init_kernel<<<4, 256>>>();
    syrk_kernel<<<dim3(36, SPLITK), 256>>>(X);
    sigred_kernel<<<1024, 256>>>();
    neumann_kernel<<<128, 256>>>(gamma);
    pred_kernel<<<2048, 256>>>(Xs, gamma, bias, out);
}

// round 5
// speedup vs baseline: 1.9829x; 1.4560x over previous
#include <cuda_runtime.h>
#include <cuda_bf16.h>
#include <cstdint>

// Problem sizes (fixed by the reference)
#define PP 16384
#define DD 1024
#define LL 128
#define SPLITK 4
#define BK 32                          // k-elements per chunk
#define NCH (PP / SPLITK / BK)         // 128 chunks per block

// ---------------------------------------------------------------------------
// Static scratch (no runtime allocation allowed)
// ---------------------------------------------------------------------------
__device__ float g_part[SPLITK][DD * DD];          // split-K partials of X^T X (16 MB)
__device__ float g_sigma[DD * DD];                 // Sigma' = X^T X (4 MB)
__device__ float g_upart[32][DD];                  // partials of X^T y
__device__ unsigned long long g_wt[2][DD];         // tagged Neumann iterate {tag,val}
__device__ float g_s[DD];                          // accumulated S @ (X^T y)
__device__ __nv_bfloat16 g_xt[2][(size_t)DD * PP]; // X^T split: hi/mid, [d][p] (64 MB)

// ---------------------------------------------------------------------------
// helpers
// ---------------------------------------------------------------------------
__device__ __forceinline__ uint32_t smem_u32(const void* p) {
    uint32_t a;
    asm("{ .reg .u64 t; cvta.to.shared.u64 t, %1; cvt.u32.u64 %0, t; }" : "=r"(a) : "l"(p));
    return a;
}
#define CP16(dst, src) \
    asm volatile("cp.async.cg.shared.global [%0], [%1], 16;" :: "r"(dst), "l"(src))
#define CP_COMMIT() asm volatile("cp.async.commit_group;" ::: "memory")
#define CP_WAIT0()  asm volatile("cp.async.wait_group 0;" ::: "memory")
#define CP_WAIT1()  asm volatile("cp.async.wait_group 1;" ::: "memory")

#define LDSM4(r, addr) \
    asm volatile("ldmatrix.sync.aligned.m8n8.x4.shared.b16 {%0,%1,%2,%3}, [%4];" \
        : "=r"((r)[0]), "=r"((r)[1]), "=r"((r)[2]), "=r"((r)[3]) : "r"(addr))
#define LDSM2(r, addr) \
    asm volatile("ldmatrix.sync.aligned.m8n8.x2.shared.b16 {%0,%1}, [%2];" \
        : "=r"((r)[0]), "=r"((r)[1]) : "r"(addr))
#define MMA16816(c, a, b) \
    asm volatile("mma.sync.aligned.m16n8k16.row.col.f32.bf16.bf16.f32 " \
        "{%0,%1,%2,%3}, {%4,%5,%6,%7}, {%8,%9}, {%0,%1,%2,%3};" \
        : "+f"((c)[0]), "+f"((c)[1]), "+f"((c)[2]), "+f"((c)[3]) \
        : "r"((a)[0]), "r"((a)[1]), "r"((a)[2]), "r"((a)[3]), "r"((b)[0]), "r"((b)[1]))

// ---------------------------------------------------------------------------
// Kernel 0: split + transpose X -> g_xt[hi/mid][d][p] bf16.
// grid (PP/64, DD/64) x 256 threads, 64x64 tiles.
// ---------------------------------------------------------------------------
__global__ void split_kernel(const float* __restrict__ X) {
    __shared__ float s[64][65];
    int p0 = blockIdx.x * 64, d0 = blockIdx.y * 64;
    int t = threadIdx.x;
    #pragma unroll
    for (int u = t; u < 64 * 64; u += 256) {
        int i = u >> 6, j = u & 63;
        s[i][j] = X[(size_t)(p0 + i) * DD + d0 + j];
    }
    __syncthreads();
    #pragma unroll
    for (int u = t; u < 64 * 64; u += 256) {
        int jj = u >> 6, ii = u & 63;
        float x = s[ii][jj];
        __nv_bfloat16 h = __float2bfloat16(x);
        float r1 = x - __bfloat162float(h);
        __nv_bfloat16 m = __float2bfloat16(r1);
        size_t o = (size_t)(d0 + jj) * PP + p0 + ii;
        g_xt[0][o] = h; g_xt[1][o] = m;
    }
}

// ---------------------------------------------------------------------------
// Kernel 1: partial X^T y.  grid (4, 32) x 256 threads.
// ---------------------------------------------------------------------------
__global__ void xty_kernel(const float* __restrict__ X, const float* __restrict__ y) {
    int r = blockIdx.x * 256 + threadIdx.x;
    int z = blockIdx.y;
    float acc = 0.f;
    int p0 = z * (PP / 32), p1 = p0 + (PP / 32);
    #pragma unroll 4
    for (int p = p0; p < p1; p++)
        acc += X[(size_t)p * DD + r] * y[p];
    g_upart[z][r] = acc;
}

// ---------------------------------------------------------------------------
// Kernel 2: reduce X^T y partials; write tagged w0 (tag=0).
// ---------------------------------------------------------------------------
__global__ void init_kernel() {
    int r = blockIdx.x * 256 + threadIdx.x;
    float acc = 0.f;
    #pragma unroll
    for (int z = 0; z < 32; z++) acc += g_upart[z][r];
    *((volatile unsigned long long*)&g_wt[0][r]) = (unsigned long long)__float_as_uint(acc);
}

// ---------------------------------------------------------------------------
// Kernel 3: HMMA SYRK via mma.sync bf16 split-2 (hh + hm + mh -> fp32 acc).
// grid (36, SPLITK) x 256 (8 warps: 2x4 warp grid, 64x32 per warp).
// SMEM: 4 tiles (Ahi, Amid, Bhi, Bmid) of 128 rows x 32 bf16, pitch 80B
// (64B data + 16B pad -> conflict-free ldmatrix), double-buffered via cp.async.
// ---------------------------------------------------------------------------
__global__ __launch_bounds__(256, 1) void syrk_mma() {
    extern __shared__ char smem[];
    const int PITCH = 80, TILE = 128 * PITCH, BUFS = 4 * TILE;  // 10240, 40960

    int tid = threadIdx.x;
    int wid = tid >> 5, lane = tid & 31;
    int wm = wid >> 2, wn = wid & 3;            // warp grid 2 x 4

    // triangular tile mapping (bi <= bj over 8x8 tile grid)
    int b = blockIdx.x, bi = 0, tt = b, rem = 8;
    while (tt >= rem) { tt -= rem; rem--; bi++; }
    int bj = bi + tt;
    int i0 = bi * 128, j0 = bj * 128;
    bool offdiag = (bi != bj);
    int z = blockIdx.y;
    int k_base = z * (PP / SPLITK);

    float acc[4][4][4];
    #pragma unroll
    for (int mt = 0; mt < 4; mt++)
        #pragma unroll
        for (int nt = 0; nt < 4; nt++)
            #pragma unroll
            for (int q = 0; q < 4; q++) acc[mt][nt][q] = 0.f;

    // chunk loader: tiles 0=Ahi 1=Amid 2=Bhi 3=Bmid; 2048 x 16B copies, 8/thread
    auto load_chunk = [&](int c, int bsel) {
        int kpos = k_base + c * BK;
        char* buf = smem + bsel * BUFS;
        #pragma unroll
        for (int q = 0; q < 8; q++) {
            int u = tid + 256 * q;
            int tl = u >> 9;            // 0..3
            int r = (u >> 2) & 127;     // row within tile
            int c16 = u & 3;            // 16B unit within row
            int arr = tl & 1;
            int rowd = ((tl < 2) ? i0 : j0) + r;
            const char* src = (const char*)(g_xt[arr] + (size_t)rowd * PP + kpos) + c16 * 16;
            uint32_t dst = smem_u32(buf + tl * TILE + r * PITCH + c16 * 16);
            CP16(dst, src);
        }
    };

    auto compute = [&](int bsel) {
        uint32_t base = smem_u32(smem + bsel * BUFS);
        uint32_t abase = base + (wm * 64 + (lane & 15)) * PITCH + (lane >> 4) * 16;
        uint32_t bbase = base + 2 * TILE + (wn * 32 + (lane & 7)) * PITCH + ((lane >> 3) & 1) * 16;
        #pragma unroll
        for (int ks = 0; ks < BK / 16; ks++) {
            uint32_t af[2][4][4];   // [arr][mt][4]
            uint32_t bf[2][4][2];   // [arr][nt][2]
            #pragma unroll
            for (int arr = 0; arr < 2; arr++)
                #pragma unroll
                for (int mt = 0; mt < 4; mt++)
                    LDSM4(af[arr][mt], abase + arr * TILE + mt * 16 * PITCH + ks * 32);
            #pragma unroll
            for (int arr = 0; arr < 2; arr++)
                #pragma unroll
                for (int nt = 0; nt < 4; nt++)
                    LDSM2(bf[arr][nt], bbase + arr * TILE + nt * 8 * PITCH + ks * 32);
            #pragma unroll
            for (int mt = 0; mt < 4; mt++)
                #pragma unroll
                for (int nt = 0; nt < 4; nt++) {
                    MMA16816(acc[mt][nt], af[0][mt], bf[0][nt]);   // hi*hi
                    MMA16816(acc[mt][nt], af[0][mt], bf[1][nt]);   // hi*mid
                    MMA16816(acc[mt][nt], af[1][mt], bf[0][nt]);   // mid*hi
                }
        }
    };

    load_chunk(0, 0);
    CP_COMMIT();
    for (int c = 0; c < NCH; c++) {
        if (c + 1 < NCH) {
            load_chunk(c + 1, (c + 1) & 1);
            CP_COMMIT();
            CP_WAIT1();
        } else {
            CP_WAIT0();
        }
        __syncthreads();
        compute(c & 1);
        __syncthreads();
    }

    // epilogue: write C tile (and mirror for off-diagonal)
    float* part = g_part[z];
    int r0 = lane >> 2, c0 = (lane & 3) * 2;
    #pragma unroll
    for (int mt = 0; mt < 4; mt++) {
        int row = i0 + wm * 64 + mt * 16 + r0;
        #pragma unroll
        for (int nt = 0; nt < 4; nt++) {
            int col = j0 + wn * 32 + nt * 8 + c0;
            float* a = acc[mt][nt];
            *(float2*)&part[(size_t)row * DD + col] = make_float2(a[0], a[1]);
            *(float2*)&part[(size_t)(row + 8) * DD + col] = make_float2(a[2], a[3]);
            if (offdiag) {
                part[(size_t)col * DD + row] = a[0];
                part[(size_t)(col + 1) * DD + row] = a[1];
                part[(size_t)col * DD + row + 8] = a[2];
                part[(size_t)(col + 1) * DD + row + 8] = a[3];
            }
        }
    }
}

// ---------------------------------------------------------------------------
// Kernel 4: reduce split-K partials into g_sigma. grid 1024 x 256 (float4).
// ---------------------------------------------------------------------------
__global__ void sigred_kernel() {
    int i = blockIdx.x * 256 + threadIdx.x;
    float4 r = ((const float4*)g_part[0])[i];
    #pragma unroll
    for (int z = 1; z < SPLITK; z++) {
        float4 a = ((const float4*)g_part[z])[i];
        r.x += a.x; r.y += a.y; r.z += a.z; r.w += a.w;
    }
    ((float4*)g_sigma)[i] = r;
}

// ---------------------------------------------------------------------------
// Kernel 5: persistent Neumann chain — all 128 iterations, dataflow sync via
// tagged 8-byte stores. grid 128 x 256 (warp r owns row r).
// ---------------------------------------------------------------------------
__global__ __launch_bounds__(256, 1) void neumann_kernel(const float* __restrict__ gamma) {
    __shared__ float ws[DD];
    int t = threadIdx.x;
    int warp = blockIdx.x * 8 + (t >> 5);
    int lane = t & 31;

    float c = (*gamma) * (1.0f / ((float)LL * (float)PP));

    const float4* row4 = (const float4*)(g_sigma + (size_t)warp * DD);
    float4 a[8];
    #pragma unroll
    for (int i = 0; i < 8; i++) a[i] = row4[i * 32 + lane];

    float s_acc = 0.f;
    for (int l = 0; l < LL; l++) {
        volatile unsigned long long* win = (volatile unsigned long long*)g_wt[l & 1];
        #pragma unroll
        for (int k = 0; k < 4; k++) {
            int j = t + 256 * k;
            unsigned long long u;
            do { u = win[j]; } while ((unsigned)(u >> 32) != (unsigned)l);
            ws[j] = __uint_as_float((unsigned)u);
        }
        __syncthreads();

        const float4* w4 = (const float4*)ws;
        float acc = 0.f;
        #pragma unroll
        for (int i = 0; i < 8; i++) {
            float4 bv = w4[i * 32 + lane];
            acc += a[i].x * bv.x + a[i].y * bv.y + a[i].z * bv.z + a[i].w * bv.w;
        }
        #pragma unroll
        for (int o = 16; o; o >>= 1) acc += __shfl_xor_sync(0xffffffffu, acc, o);

        if (lane == 0) {
            float wv = ws[warp];
            s_acc += wv;
            float wn = wv - c * acc;
            unsigned long long u = ((unsigned long long)(unsigned)(l + 1) << 32)
                                 | (unsigned long long)__float_as_uint(wn);
            *((volatile unsigned long long*)&g_wt[(l + 1) & 1][warp]) = u;
        }
        __syncthreads();
    }
    if (lane == 0) g_s[warp] = s_acc;
}

// ---------------------------------------------------------------------------
// Kernel 6: predictions = (gamma/(L*P)) * (X_star @ s) + bias. grid 2048 x 256.
// ---------------------------------------------------------------------------
__global__ void pred_kernel(const float* __restrict__ Xs,
                            const float* __restrict__ gamma,
                            const float* __restrict__ bias,
                            float* __restrict__ out) {
    __shared__ float ss[DD];
    int t = threadIdx.x;
    #pragma unroll
    for (int i = t; i < DD; i += 256) ss[i] = g_s[i];
    __syncthreads();

    int warp = blockIdx.x * 8 + (t >> 5);
    int lane = t & 31;
    const float4* row4 = (const float4*)(Xs + (size_t)warp * DD);
    const float4* s4 = (const float4*)ss;
    float acc = 0.f;
    #pragma unroll
    for (int j = lane; j < DD / 4; j += 32) {
        float4 a = row4[j], bv = s4[j];
        acc += a.x * bv.x + a.y * bv.y + a.z * bv.z + a.w * bv.w;
    }
    #pragma unroll
    for (int o = 16; o; o >>= 1) acc += __shfl_xor_sync(0xffffffffu, acc, o);
    if (lane == 0) {
        float sc = (*gamma) * (1.0f / ((float)LL * (float)PP));
        out[warp] = sc * acc + (*bias);
    }
}

// ---------------------------------------------------------------------------
extern "C" void kernel_launch(void* const* d_in, const int* in_sizes, int n_in,
                              void* d_out, int out_size) {
    const float* X     = (const float*)d_in[0];
    const float* y     = (const float*)d_in[1];
    const float* Xs    = (const float*)d_in[2];
    const float* gamma = (const float*)d_in[3];
    const float* bias  = (const float*)d_in[4];
    float* out = (float*)d_out;

    const int SMEM_DYN = 2 * 40960;   // 81920 bytes
    cudaFuncSetAttribute(syrk_mma, cudaFuncAttributeMaxDynamicSharedMemorySize, SMEM_DYN);

    split_kernel<<<dim3(PP / 64, DD / 64), 256>>>(X);
    xty_kernel<<<dim3(4, 32), 256>>>(X, y);
    init_kernel<<<4, 256>>>();
    syrk_mma<<<dim3(36, SPLITK), 256, SMEM_DYN>>>();
    sigred_kernel<<<1024, 256>>>();
    neumann_kernel<<<128, 256>>>(gamma);
    pred_kernel<<<2048, 256>>>(Xs, gamma, bias, out);
}

// round 6
// speedup vs baseline: 2.4974x; 1.2595x over previous
#include <cuda_runtime.h>
#include <cuda_bf16.h>
#include <cstdint>

// Problem sizes (fixed by the reference)
#define PP 16384
#define DD 1024
#define LL 128
#define SPLITK 4
#define BK 32                          // k-elements per chunk

// ---------------------------------------------------------------------------
// Static scratch (no runtime allocation allowed)
// ---------------------------------------------------------------------------
__device__ float g_part[SPLITK][DD * DD];          // split-K partials (16 MB, reused)
__device__ float g_m[DD * DD];                     // M fp32 (4 MB)
__device__ float g_m2[DD * DD];                    // M^2 fp32 (4 MB)
__device__ float g_m4[DD * DD];                    // M^4 fp32 (4 MB)
__device__ __nv_bfloat16 g_mh[2][DD * DD];         // M split hi/mid (4 MB)
__device__ __nv_bfloat16 g_m2h[2][DD * DD];        // M^2 split hi/mid (4 MB)
__device__ float g_upart[32][DD];                  // partials of X^T y
__device__ unsigned long long g_wt[2][DD];         // tagged chain iterate {tag,val}
__device__ float g_s[DD];                          // accumulated S @ (X^T y)
__device__ __nv_bfloat16 g_xt[2][(size_t)DD * PP]; // X^T split hi/mid, [d][p] (64 MB)

// ---------------------------------------------------------------------------
// helpers
// ---------------------------------------------------------------------------
__device__ __forceinline__ uint32_t smem_u32(const void* p) {
    uint32_t a;
    asm("{ .reg .u64 t; cvta.to.shared.u64 t, %1; cvt.u32.u64 %0, t; }" : "=r"(a) : "l"(p));
    return a;
}
#define CP16(dst, src) \
    asm volatile("cp.async.cg.shared.global [%0], [%1], 16;" :: "r"(dst), "l"(src))
#define CP_COMMIT() asm volatile("cp.async.commit_group;" ::: "memory")
#define CP_WAIT0()  asm volatile("cp.async.wait_group 0;" ::: "memory")
#define CP_WAIT1()  asm volatile("cp.async.wait_group 1;" ::: "memory")

#define LDSM4(r, addr) \
    asm volatile("ldmatrix.sync.aligned.m8n8.x4.shared.b16 {%0,%1,%2,%3}, [%4];" \
        : "=r"((r)[0]), "=r"((r)[1]), "=r"((r)[2]), "=r"((r)[3]) : "r"(addr))
#define LDSM2(r, addr) \
    asm volatile("ldmatrix.sync.aligned.m8n8.x2.shared.b16 {%0,%1}, [%2];" \
        : "=r"((r)[0]), "=r"((r)[1]) : "r"(addr))
#define MMA16816(c, a, b) \
    asm volatile("mma.sync.aligned.m16n8k16.row.col.f32.bf16.bf16.f32 " \
        "{%0,%1,%2,%3}, {%4,%5,%6,%7}, {%8,%9}, {%0,%1,%2,%3};" \
        : "+f"((c)[0]), "+f"((c)[1]), "+f"((c)[2]), "+f"((c)[3]) \
        : "r"((a)[0]), "r"((a)[1]), "r"((a)[2]), "r"((a)[3]), "r"((b)[0]), "r"((b)[1]))

// ---------------------------------------------------------------------------
// Kernel 0: split + transpose X -> g_xt[hi/mid][d][p] bf16.
// ---------------------------------------------------------------------------
__global__ void split_kernel(const float* __restrict__ X) {
    __shared__ float s[64][65];
    int p0 = blockIdx.x * 64, d0 = blockIdx.y * 64;
    int t = threadIdx.x;
    #pragma unroll
    for (int u = t; u < 64 * 64; u += 256) {
        int i = u >> 6, j = u & 63;
        s[i][j] = X[(size_t)(p0 + i) * DD + d0 + j];
    }
    __syncthreads();
    #pragma unroll
    for (int u = t; u < 64 * 64; u += 256) {
        int jj = u >> 6, ii = u & 63;
        float x = s[ii][jj];
        __nv_bfloat16 h = __float2bfloat16(x);
        float r1 = x - __bfloat162float(h);
        __nv_bfloat16 m = __float2bfloat16(r1);
        size_t o = (size_t)(d0 + jj) * PP + p0 + ii;
        g_xt[0][o] = h; g_xt[1][o] = m;
    }
}

// ---------------------------------------------------------------------------
// Kernel 1: partial X^T y.  grid (4, 32) x 256 threads.
// ---------------------------------------------------------------------------
__global__ void xty_kernel(const float* __restrict__ X, const float* __restrict__ y) {
    int r = blockIdx.x * 256 + threadIdx.x;
    int z = blockIdx.y;
    float acc = 0.f;
    int p0 = z * (PP / 32), p1 = p0 + (PP / 32);
    #pragma unroll 4
    for (int p = p0; p < p1; p++)
        acc += X[(size_t)p * DD + r] * y[p];
    g_upart[z][r] = acc;
}

// ---------------------------------------------------------------------------
// Kernel 2: reduce X^T y partials; write tagged w0 (tag=0).
// ---------------------------------------------------------------------------
__global__ void init_kernel() {
    int r = blockIdx.x * 256 + threadIdx.x;
    float acc = 0.f;
    #pragma unroll
    for (int z = 0; z < 32; z++) acc += g_upart[z][r];
    *((volatile unsigned long long*)&g_wt[0][r]) = (unsigned long long)__float_as_uint(acc);
}

// ---------------------------------------------------------------------------
// Kernel 3: generic HMMA SYRK: g_part[z] += A-rows . A-rows^T over a K range.
// A given as bf16 hi/mid pair, row pitch `pitch`, split section `ksplit`.
// grid (36, SPLITK) x 256 (8 warps: 2x4 warp grid, 64x32 per warp).
// Products ordered outermost (hh, hm, mh) for accumulator independence.
// ---------------------------------------------------------------------------
__global__ __launch_bounds__(256, 1) void syrk_mma(const __nv_bfloat16* __restrict__ hi,
                                                   const __nv_bfloat16* __restrict__ mid,
                                                   int pitch, int ksplit) {
    extern __shared__ char smem[];
    const int PITCH = 80, TILE = 128 * PITCH, BUFS = 4 * TILE;  // 10240, 40960
    const int nch = ksplit / BK;

    int tid = threadIdx.x;
    int wid = tid >> 5, lane = tid & 31;
    int wm = wid >> 2, wn = wid & 3;            // warp grid 2 x 4

    // triangular tile mapping (bi <= bj over 8x8 tile grid)
    int b = blockIdx.x, bi = 0, tt = b, rem = 8;
    while (tt >= rem) { tt -= rem; rem--; bi++; }
    int bj = bi + tt;
    int i0 = bi * 128, j0 = bj * 128;
    bool offdiag = (bi != bj);
    int z = blockIdx.y;
    int k_base = z * ksplit;

    float acc[4][4][4];
    #pragma unroll
    for (int mt = 0; mt < 4; mt++)
        #pragma unroll
        for (int nt = 0; nt < 4; nt++)
            #pragma unroll
            for (int q = 0; q < 4; q++) acc[mt][nt][q] = 0.f;

    // chunk loader: tiles 0=Ahi 1=Amid 2=Bhi 3=Bmid; 2048 x 16B copies, 8/thread
    auto load_chunk = [&](int c, int bsel) {
        int kpos = k_base + c * BK;
        char* buf = smem + bsel * BUFS;
        #pragma unroll
        for (int q = 0; q < 8; q++) {
            int u = tid + 256 * q;
            int tl = u >> 9;            // 0..3
            int r = (u >> 2) & 127;     // row within tile
            int c16 = u & 3;            // 16B unit within row
            const __nv_bfloat16* base = (tl & 1) ? mid : hi;
            int rowd = ((tl < 2) ? i0 : j0) + r;
            const char* src = (const char*)(base + (size_t)rowd * pitch + kpos) + c16 * 16;
            uint32_t dst = smem_u32(buf + tl * TILE + r * PITCH + c16 * 16);
            CP16(dst, src);
        }
    };

    const int aSel[3] = {0, 0, 1};
    const int bSel[3] = {0, 1, 0};

    auto compute = [&](int bsel) {
        uint32_t base = smem_u32(smem + bsel * BUFS);
        uint32_t abase = base + (wm * 64 + (lane & 15)) * PITCH + (lane >> 4) * 16;
        uint32_t bbase = base + 2 * TILE + (wn * 32 + (lane & 7)) * PITCH + ((lane >> 3) & 1) * 16;
        #pragma unroll
        for (int ks = 0; ks < BK / 16; ks++) {
            uint32_t af[2][4][4];   // [arr][mt][4]
            uint32_t bf[2][4][2];   // [arr][nt][2]
            #pragma unroll
            for (int arr = 0; arr < 2; arr++)
                #pragma unroll
                for (int mt = 0; mt < 4; mt++)
                    LDSM4(af[arr][mt], abase + arr * TILE + mt * 16 * PITCH + ks * 32);
            #pragma unroll
            for (int arr = 0; arr < 2; arr++)
                #pragma unroll
                for (int nt = 0; nt < 4; nt++)
                    LDSM2(bf[arr][nt], bbase + arr * TILE + nt * 8 * PITCH + ks * 32);
            // products outermost: 16 independent accumulators between reuses
            #pragma unroll
            for (int pi = 0; pi < 3; pi++)
                #pragma unroll
                for (int mt = 0; mt < 4; mt++)
                    #pragma unroll
                    for (int nt = 0; nt < 4; nt++)
                        MMA16816(acc[mt][nt], af[aSel[pi]][mt], bf[bSel[pi]][nt]);
        }
    };

    load_chunk(0, 0);
    CP_COMMIT();
    for (int c = 0; c < nch; c++) {
        if (c + 1 < nch) {
            load_chunk(c + 1, (c + 1) & 1);
            CP_COMMIT();
            CP_WAIT1();
        } else {
            CP_WAIT0();
        }
        __syncthreads();
        compute(c & 1);
        __syncthreads();
    }

    // epilogue: write C tile (and mirror for off-diagonal)
    float* part = g_part[z];
    int r0 = lane >> 2, c0 = (lane & 3) * 2;
    #pragma unroll
    for (int mt = 0; mt < 4; mt++) {
        int row = i0 + wm * 64 + mt * 16 + r0;
        #pragma unroll
        for (int nt = 0; nt < 4; nt++) {
            int col = j0 + wn * 32 + nt * 8 + c0;
            float* a = acc[mt][nt];
            *(float2*)&part[(size_t)row * DD + col] = make_float2(a[0], a[1]);
            *(float2*)&part[(size_t)(row + 8) * DD + col] = make_float2(a[2], a[3]);
            if (offdiag) {
                part[(size_t)col * DD + row] = a[0];
                part[(size_t)(col + 1) * DD + row] = a[1];
                part[(size_t)col * DD + row + 8] = a[2];
                part[(size_t)(col + 1) * DD + row + 8] = a[3];
            }
        }
    }
}

// ---------------------------------------------------------------------------
// Kernel 4: reduce split-K partials -> fp32 matrix (+ optional bf16 split,
// + optional build of M = I - c*Sigma).  grid 1024 x 256, float4 per thread.
// ---------------------------------------------------------------------------
__global__ void reduce_kernel(float* __restrict__ outf,
                              __nv_bfloat16* __restrict__ outh,
                              __nv_bfloat16* __restrict__ outm,
                              const float* __restrict__ gamma, int build) {
    int i = blockIdx.x * 256 + threadIdx.x;   // float4 index, 262144 total
    float4 r = ((const float4*)g_part[0])[i];
    #pragma unroll
    for (int z = 1; z < SPLITK; z++) {
        float4 a = ((const float4*)g_part[z])[i];
        r.x += a.x; r.y += a.y; r.z += a.z; r.w += a.w;
    }
    if (build) {
        float c = (*gamma) * (1.0f / ((float)LL * (float)PP));
        int e = i * 4, row = e >> 10, col = e & 1023;
        r.x = ((row == col + 0) ? 1.f : 0.f) - c * r.x;
        r.y = ((row == col + 1) ? 1.f : 0.f) - c * r.y;
        r.z = ((row == col + 2) ? 1.f : 0.f) - c * r.z;
        r.w = ((row == col + 3) ? 1.f : 0.f) - c * r.w;
    }
    ((float4*)outf)[i] = r;
    if (outh) {
        float v[4] = {r.x, r.y, r.z, r.w};
        int e = i * 4;
        #pragma unroll
        for (int q = 0; q < 4; q++) {
            __nv_bfloat16 h = __float2bfloat16(v[q]);
            outh[e + q] = h;
            outm[e + q] = __float2bfloat16(v[q] - __bfloat162float(h));
        }
    }
}

// ---------------------------------------------------------------------------
// Kernel 5: 34-step chain:  s = (I+M)(I+M^2) applied, then 32 steps on M^4.
// grid 128 x 256 (warp r owns row r). Dataflow sync via tagged 8-byte stores.
//   step 0: w1 = w0 + M  w0   (M rows streamed from global)
//   step 1: w2 = w1 + M^2 w1  (M^2 rows streamed)
//   steps 2..33: s += w; w' = M^4 w  (M^4 row in registers)
// ---------------------------------------------------------------------------
__global__ __launch_bounds__(256, 1) void chain_kernel() {
    __shared__ float ws[DD];
    int t = threadIdx.x;
    int warp = blockIdx.x * 8 + (t >> 5);
    int lane = t & 31;

    const float4* m4row = (const float4*)(g_m4 + (size_t)warp * DD);
    float4 a[8];
    #pragma unroll
    for (int i = 0; i < 8; i++) a[i] = m4row[i * 32 + lane];

    float s_acc = 0.f;
    for (int l = 0; l < 34; l++) {
        volatile unsigned long long* win = (volatile unsigned long long*)g_wt[l & 1];
        #pragma unroll
        for (int k = 0; k < 4; k++) {
            int j = t + 256 * k;
            unsigned long long u;
            do { u = win[j]; } while ((unsigned)(u >> 32) != (unsigned)l);
            ws[j] = __uint_as_float((unsigned)u);
        }
        __syncthreads();

        const float4* w4 = (const float4*)ws;
        float dot = 0.f;
        if (l < 2) {
            const float4* row = (const float4*)((l == 0 ? g_m : g_m2) + (size_t)warp * DD);
            #pragma unroll
            for (int i = 0; i < 8; i++) {
                float4 av = row[i * 32 + lane], bv = w4[i * 32 + lane];
                dot += av.x * bv.x + av.y * bv.y + av.z * bv.z + av.w * bv.w;
            }
        } else {
            #pragma unroll
            for (int i = 0; i < 8; i++) {
                float4 bv = w4[i * 32 + lane];
                dot += a[i].x * bv.x + a[i].y * bv.y + a[i].z * bv.z + a[i].w * bv.w;
            }
        }
        #pragma unroll
        for (int o = 16; o; o >>= 1) dot += __shfl_xor_sync(0xffffffffu, dot, o);

        if (lane == 0) {
            float wv = ws[warp];
            float outv;
            if (l < 2) outv = wv + dot;          // (I + M^{2^l}) w
            else       { s_acc += wv; outv = dot; }  // accumulate, w' = M^4 w
            unsigned long long u = ((unsigned long long)(unsigned)(l + 1) << 32)
                                 | (unsigned long long)__float_as_uint(outv);
            *((volatile unsigned long long*)&g_wt[(l + 1) & 1][warp]) = u;
        }
        __syncthreads();
    }
    if (lane == 0) g_s[warp] = s_acc;
}

// ---------------------------------------------------------------------------
// Kernel 6: predictions = (gamma/(L*P)) * (X_star @ s) + bias. grid 2048 x 256.
// ---------------------------------------------------------------------------
__global__ void pred_kernel(const float* __restrict__ Xs,
                            const float* __restrict__ gamma,
                            const float* __restrict__ bias,
                            float* __restrict__ out) {
    __shared__ float ss[DD];
    int t = threadIdx.x;
    #pragma unroll
    for (int i = t; i < DD; i += 256) ss[i] = g_s[i];
    __syncthreads();

    int warp = blockIdx.x * 8 + (t >> 5);
    int lane = t & 31;
    const float4* row4 = (const float4*)(Xs + (size_t)warp * DD);
    const float4* s4 = (const float4*)ss;
    float acc = 0.f;
    #pragma unroll
    for (int j = lane; j < DD / 4; j += 32) {
        float4 a = row4[j], bv = s4[j];
        acc += a.x * bv.x + a.y * bv.y + a.z * bv.z + a.w * bv.w;
    }
    #pragma unroll
    for (int o = 16; o; o >>= 1) acc += __shfl_xor_sync(0xffffffffu, acc, o);
    if (lane == 0) {
        float sc = (*gamma) * (1.0f / ((float)LL * (float)PP));
        out[warp] = sc * acc + (*bias);
    }
}

// ---------------------------------------------------------------------------
extern "C" void kernel_launch(void* const* d_in, const int* in_sizes, int n_in,
                              void* d_out, int out_size) {
    const float* X     = (const float*)d_in[0];
    const float* y     = (const float*)d_in[1];
    const float* Xs    = (const float*)d_in[2];
    const float* gamma = (const float*)d_in[3];
    const float* bias  = (const float*)d_in[4];
    float* out = (float*)d_out;

    const int SMEM_DYN = 2 * 40960;   // 81920 bytes
    cudaFuncSetAttribute(syrk_mma, cudaFuncAttributeMaxDynamicSharedMemorySize, SMEM_DYN);

    __nv_bfloat16 *xh, *xm, *mh, *mm, *m2h, *m2m;
    cudaGetSymbolAddress((void**)&xh, g_xt);  // [0] then [1] contiguous
    xm = xh + (size_t)DD * PP;
    cudaGetSymbolAddress((void**)&mh, g_mh);
    mm = mh + (size_t)DD * DD;
    cudaGetSymbolAddress((void**)&m2h, g_m2h);
    m2m = m2h + (size_t)DD * DD;
    float *pm, *pm2, *pm4;
    cudaGetSymbolAddress((void**)&pm, g_m);
    cudaGetSymbolAddress((void**)&pm2, g_m2);
    cudaGetSymbolAddress((void**)&pm4, g_m4);

    split_kernel<<<dim3(PP / 64, DD / 64), 256>>>(X);
    xty_kernel<<<dim3(4, 32), 256>>>(X, y);
    init_kernel<<<4, 256>>>();
    // Sigma partials = X^T X
    syrk_mma<<<dim3(36, SPLITK), 256, SMEM_DYN>>>(xh, xm, PP, PP / SPLITK);
    // M = I - c*Sigma (fp32 + bf16 split)
    reduce_kernel<<<1024, 256>>>(pm, mh, mm, gamma, 1);
    // M^2 = M . M^T  (M symmetric)
    syrk_mma<<<dim3(36, SPLITK), 256, SMEM_DYN>>>(mh, mm, DD, DD / SPLITK);
    reduce_kernel<<<1024, 256>>>(pm2, m2h, m2m, gamma, 0);
    // M^4 = M^2 . M^2^T
    syrk_mma<<<dim3(36, SPLITK), 256, SMEM_DYN>>>(m2h, m2m, DD, DD / SPLITK);
    reduce_kernel<<<1024, 256>>>(pm4, (__nv_bfloat16*)0, (__nv_bfloat16*)0, gamma, 0);
    // 34-step chain + prediction
    chain_kernel<<<128, 256>>>();
    pred_kernel<<<2048, 256>>>(Xs, gamma, bias, out);
}